// round 16
// baseline (speedup 1.0000x reference)
#include <cuda_runtime.h>

// Problem constants
#define N_PRE       20000
#define VEC_DIM     300
#define INPUT_SIZE  10000
#define HIDDEN      256
#define OUT_DIM     556
#define N_TOKENS    4096
#define VEC4        (VEC_DIM / 4)          // 75

// Transposed weights with bias pre-added: g_Wt[c*256 + h] = W[h][c] + b[h].
// 10.24 MB static scratch (allowed).
__device__ float g_Wt[(size_t)INPUT_SIZE * HIDDEN];

// ---------------------------------------------------------------------------
// Kernel 1: tiled transpose + bias fuse. W[256,10000] -> Wt[10000,256]+b.
// 32x32 tiles, coalesced both sides. Demonstrated ~5.7 TB/s in R11.
// ---------------------------------------------------------------------------
__global__ __launch_bounds__(256)
void transpose_kernel(const float* __restrict__ W, const float* __restrict__ b)
{
    __shared__ float tile[32][33];

    const int c0 = blockIdx.x * 32;
    const int h0 = blockIdx.y * 32;
    const int tx = threadIdx.x;   // 0..31
    const int ty = threadIdx.y;   // 0..7

#pragma unroll
    for (int i = 0; i < 32; i += 8) {
        const int c = c0 + tx;
        const int h = h0 + ty + i;           // < 256 always
        if (c < INPUT_SIZE)
            tile[ty + i][tx] = W[(size_t)h * INPUT_SIZE + c];
    }
    const float bias = b[h0 + tx];           // reused for all 4 writes
    __syncthreads();
#pragma unroll
    for (int i = 0; i < 32; i += 8) {
        const int c = c0 + ty + i;
        const int h = h0 + tx;
        if (c < INPUT_SIZE)
            g_Wt[(size_t)c * HIDDEN + h] = tile[tx][ty + i] + bias;
    }
}

// ---------------------------------------------------------------------------
// Kernel 2: vector part, flat item-per-thread. 307200 float4 items.
//   out[tok][0:300] = t<N_PRE ? vectors[t] : 0
// Runs on a side stream, fully overlapped with the transpose.
// ---------------------------------------------------------------------------
#define VEC_ITEMS  (N_TOKENS * VEC4)              // 307200
#define VEC_GRID   ((VEC_ITEMS + 255) / 256)      // 1200

__global__ __launch_bounds__(256)
void vector_kernel(const int* __restrict__ batch,
                   const float* __restrict__ vectors,
                   float* __restrict__ out)
{
    const int k = blockIdx.x * 256 + threadIdx.x;
    if (k >= VEC_ITEMS) return;
    const int tok = k / VEC4;
    const int q   = k - tok * VEC4;
    const int t   = batch[tok];               // ~2-3 distinct per warp
    float4 v = make_float4(0.f, 0.f, 0.f, 0.f);
    if (t < N_PRE)
        v = reinterpret_cast<const float4*>(vectors + (size_t)t * VEC_DIM)[q];
    reinterpret_cast<float4*>(out + (size_t)tok * OUT_DIM)[q] = v;   // 16B aligned
}

// ---------------------------------------------------------------------------
// Kernel 3: hidden part from transposed+biased Wt. Flat float4 items.
//   out[tok][300+4q..] = t>=N_PRE ? Wt[(t-N_PRE)*256 + 4q..] : b[4q..]
// 262144 items -> 1024 blocks. Fully coalesced; ~8 wavefronts/token.
// ---------------------------------------------------------------------------
#define HID_ITEMS  (N_TOKENS * (HIDDEN / 4))      // 262144
#define HID_GRID   (HID_ITEMS / 256)              // 1024

__global__ __launch_bounds__(256)
void hidden_kernel(const int* __restrict__ batch,
                   const float* __restrict__ b,
                   float* __restrict__ out)
{
    const int k   = blockIdx.x * 256 + threadIdx.x;
    const int tok = k >> 6;                    // /64 (64 float4 per token)
    const int q   = k & 63;
    const int t   = batch[tok];                // 1-2 distinct per warp
    float4 r;
    if (t >= N_PRE)
        r = reinterpret_cast<const float4*>(g_Wt + (size_t)(t - N_PRE) * HIDDEN)[q];
    else
        r = reinterpret_cast<const float4*>(b)[q];
    // out + tok*556 + 300 : 2224B*tok + 1200B -> 16B aligned
    reinterpret_cast<float4*>(out + (size_t)tok * OUT_DIM + VEC_DIM)[q] = r;
}

extern "C" void kernel_launch(void* const* d_in, const int* in_sizes, int n_in,
                              void* d_out, int out_size)
{
    const int*   batch   = (const int*)  d_in[0];
    const float* vectors = (const float*)d_in[1];
    const float* W       = (const float*)d_in[2];
    const float* b       = (const float*)d_in[3];
    float*       out     = (float*)d_out;

    // Fork/join diamond (capture-legal; host-side stream/event objects only):
    //   null stream: transpose -> hidden   (hidden depends on g_Wt)
    //   side stream: vector copy           (independent, overlaps transpose)
    cudaStream_t s2;
    cudaStreamCreateWithFlags(&s2, cudaStreamNonBlocking);
    cudaEvent_t eFork, eJoin;
    cudaEventCreateWithFlags(&eFork, cudaEventDisableTiming);
    cudaEventCreateWithFlags(&eJoin, cudaEventDisableTiming);

    cudaEventRecord(eFork, 0);
    cudaStreamWaitEvent(s2, eFork, 0);

    dim3 tgrid((INPUT_SIZE + 31) / 32, HIDDEN / 32);   // (313, 8)
    dim3 tblk(32, 8);
    transpose_kernel<<<tgrid, tblk, 0, 0>>>(W, b);
    vector_kernel<<<VEC_GRID, 256, 0, s2>>>(batch, vectors, out);
    hidden_kernel<<<HID_GRID, 256, 0, 0>>>(batch, b, out);

    cudaEventRecord(eJoin, s2);
    cudaStreamWaitEvent(0, eJoin, 0);

    cudaEventDestroy(eFork);
    cudaEventDestroy(eJoin);
    cudaStreamDestroy(s2);
}